// round 4
// baseline (speedup 1.0000x reference)
#include <cuda_runtime.h>
#include <cstdint>
#include <cstddef>

#define NUSERS 100000
#define NITEMS 100000
#define DIN 128
#define DOUT 128
#define NSUP 5
#define NEDGE 500000
#define MTILES ((NUSERS + 127) / 128)
#define NBINS (2 * NSUP * NUSERS)          // 1,000,000 bins (side,s,row)
#define NCHUNK ((NBINS + 1023) / 1024)     // 977
#define TOTE (2 * NSUP * NEDGE)            // 5,000,000 edges

// ---------------------------------------------------------------------------
// Device scratch
// ---------------------------------------------------------------------------
__device__ float g_Wc[NSUP][DIN * DOUT];   // tf32-rounded cumulative W
__device__ int g_cnt[NBINS];               // histogram, then cursor
__device__ int g_off[NBINS + 1];           // CSR offsets
__device__ int g_blksum[1024];             // scan block sums
__device__ int2 g_edges[TOTE];             // {col, val_bits} binned by (side,s,row)

// ---------------------------------------------------------------------------
// Cumulative weight, rounded to tf32.  weight layout [din][dout][s]
// ---------------------------------------------------------------------------
__global__ void wcum_kernel(const float* __restrict__ w) {
    int din = blockIdx.x;
    int dout = threadIdx.x;
    const float* p = w + ((size_t)din * DOUT + dout) * NSUP;
    float acc = 0.f;
#pragma unroll
    for (int s = 0; s < NSUP; s++) {
        acc += p[s];
        uint32_t r;
        asm("cvt.rna.tf32.f32 %0, %1;" : "=r"(r) : "f"(acc));
        g_Wc[s][din * DOUT + dout] = __uint_as_float(r);
    }
}

// ---------------------------------------------------------------------------
// CSR build: zero -> histogram -> scan(3) -> scatter
// bin = (side*NSUP + s)*NUSERS + row
// ---------------------------------------------------------------------------
__global__ void zero_kernel() {
    int i = blockIdx.x * 256 + threadIdx.x;
    if (i < NBINS) g_cnt[i] = 0;
}

__global__ void hist_kernel(const int* __restrict__ rows, int sidebase) {
    int e = blockIdx.x * 256 + threadIdx.x;
    if (e >= NSUP * NEDGE) return;
    int s = e / NEDGE;
    int bin = (sidebase * NSUP + s) * NUSERS + __ldg(&rows[e]);
    atomicAdd(&g_cnt[bin], 1);
}

__global__ __launch_bounds__(256) void scan1_kernel() {
    __shared__ int s0[256], s1[256];
    int b = blockIdx.x, tid = threadIdx.x;
    int base = b * 1024 + tid * 4;
    int v[4];
#pragma unroll
    for (int j = 0; j < 4; j++) {
        int idx = base + j;
        v[j] = (idx < NBINS) ? g_cnt[idx] : 0;
    }
    int tsum = v[0] + v[1] + v[2] + v[3];
    s0[tid] = tsum;
    __syncthreads();
    int* src = s0;
    int* dst = s1;
#pragma unroll
    for (int o = 1; o < 256; o <<= 1) {
        int x = src[tid];
        if (tid >= o) x += src[tid - o];
        __syncthreads();
        dst[tid] = x;
        __syncthreads();
        int* tmp = src; src = dst; dst = tmp;
    }
    int run = (tid == 0) ? 0 : src[tid - 1];
#pragma unroll
    for (int j = 0; j < 4; j++) {
        int idx = base + j;
        if (idx < NBINS) g_off[idx] = run;
        run += v[j];
    }
    if (tid == 255) g_blksum[b] = src[255];
}

__global__ __launch_bounds__(1024) void scan2_kernel() {
    __shared__ int s0[1024], s1[1024];
    int tid = threadIdx.x;
    s0[tid] = (tid < NCHUNK) ? g_blksum[tid] : 0;
    __syncthreads();
    int* src = s0;
    int* dst = s1;
#pragma unroll
    for (int o = 1; o < 1024; o <<= 1) {
        int x = src[tid];
        if (tid >= o) x += src[tid - o];
        __syncthreads();
        dst[tid] = x;
        __syncthreads();
        int* tmp = src; src = dst; dst = tmp;
    }
    int excl = (tid == 0) ? 0 : src[tid - 1];
    if (tid < NCHUNK) g_blksum[tid] = excl;
    if (tid == 0) g_off[NBINS] = TOTE;
}

__global__ __launch_bounds__(256) void scan3_kernel() {
    int b = blockIdx.x;
    int add = g_blksum[b];
#pragma unroll
    for (int j = 0; j < 4; j++) {
        int idx = b * 1024 + threadIdx.x + 256 * j;
        if (idx < NBINS) {
            int o = g_off[idx] + add;
            g_off[idx] = o;
            g_cnt[idx] = o;  // cursor init
        }
    }
}

__global__ void scatter_kernel(const int* __restrict__ rows,
                               const int* __restrict__ cols,
                               const float* __restrict__ vals, int sidebase) {
    int e = blockIdx.x * 256 + threadIdx.x;
    if (e >= NSUP * NEDGE) return;
    int s = e / NEDGE;
    int bin = (sidebase * NSUP + s) * NUSERS + __ldg(&rows[e]);
    int pos = atomicAdd(&g_cnt[bin], 1);
    g_edges[pos] = make_int2(__ldg(&cols[e]), __float_as_int(__ldg(&vals[e])));
}

// ---------------------------------------------------------------------------
// FUSED gather + tensor GEMM + ReLU.
// Block = 256 thr (8 warps), tile 128(M) x 128(N), grid (MTILES, 2).
// Per support s: gather this tile's rows (A = A_s @ inputs slice) into smem,
// then MMA against Wc[s] (cp.async double-buffered K chunks), accumulating C.
// ---------------------------------------------------------------------------
#define KC 16
#define ASTR 132   // 128+4 words: frag reads gid*4+tig cover banks 0..31
#define BSTR 136   // frag reads tig*8+gid cover banks 0..31

__device__ __forceinline__ void cp16(float* sdst, const float* gsrc) {
    unsigned u = (unsigned)__cvta_generic_to_shared(sdst);
    asm volatile("cp.async.cg.shared.global [%0], [%1], 16;" :: "r"(u), "l"(gsrc));
}

#define MMA_TF32(c, a, b)                                                    \
    asm volatile(                                                            \
        "mma.sync.aligned.m16n8k8.row.col.f32.tf32.tf32.f32 "               \
        "{%0,%1,%2,%3}, {%4,%5,%6,%7}, {%8,%9}, {%0,%1,%2,%3};"             \
        : "+f"(c[0]), "+f"(c[1]), "+f"(c[2]), "+f"(c[3])                     \
        : "r"(a[0]), "r"(a[1]), "r"(a[2]), "r"(a[3]), "r"(b[0]), "r"(b[1]))

__global__ __launch_bounds__(256, 2) void fused_kernel(const float* __restrict__ U,
                                                       const float* __restrict__ It,
                                                       float* __restrict__ out) {
    const int side = blockIdx.y;
    const int row0 = blockIdx.x * 128;
    // user dest gathers from item inputs, item dest from user inputs
    const float4* __restrict__ src = (const float4*)(side == 0 ? It : U);

    __shared__ float sA[128 * ASTR];     // 67.6 KB
    __shared__ float sB[2][KC * BSTR];   // 17.4 KB

    const int t = threadIdx.x;
    const int wid = t >> 5;
    const int lane = t & 31;
    const int gid = lane >> 2;  // 0..7
    const int tig = lane & 3;   // 0..3
    const int wm = (wid & 3) * 32;
    const int wn = (wid >> 2) * 64;

    float c[2][8][4];
#pragma unroll
    for (int mt = 0; mt < 2; mt++)
#pragma unroll
        for (int nt = 0; nt < 8; nt++)
#pragma unroll
            for (int i = 0; i < 4; i++) c[mt][nt][i] = 0.f;

    // B chunk copy: 16 k-rows x 128 floats = 512 quads, 2 per thread
    auto copyB = [&](int s, int kc, int b) {
        const float* Bsrc = g_Wc[s] + (size_t)kc * KC * 128;
#pragma unroll
        for (int i = 0; i < 2; i++) {
            int q = t + 256 * i;
            int kr = q >> 5, c4 = (q & 31) * 4;
            cp16(&sB[b][kr * BSTR + c4], Bsrc + (size_t)kr * 128 + c4);
        }
        asm volatile("cp.async.commit_group;");
    };

#pragma unroll 1
    for (int s = 0; s < NSUP; s++) {
        // prefetch first B chunk of this support; overlaps the gather below
        copyB(s, 0, 0);

        // ---- gather A tile: warp handles 16 rows, lane covers 4 cols ----
        const int rbase = wid * 16;
        const int binbase = (side * NSUP + s) * NUSERS;
#pragma unroll 1
        for (int rr = 0; rr < 16; rr++) {
            int row = row0 + rbase + rr;
            float4 acc = make_float4(0.f, 0.f, 0.f, 0.f);
            if (row < NUSERS) {
                int e0 = __ldg(&g_off[binbase + row]);
                int e1 = __ldg(&g_off[binbase + row + 1]);
                for (int e = e0; e < e1; e++) {
                    int2 p = __ldg(&g_edges[e]);
                    float v = __int_as_float(p.y);
                    float4 x = __ldg(&src[(size_t)p.x * 32 + lane]);
                    acc.x += v * x.x;
                    acc.y += v * x.y;
                    acc.z += v * x.z;
                    acc.w += v * x.w;
                }
            }
            *(float4*)&sA[(rbase + rr) * ASTR + lane * 4] = acc;
        }
        __syncthreads();  // A tile ready (B chunk0 handled by wait in loop)

        // ---- MMA over K=128 for this support, KC=16 double-buffered B ----
        int buf = 0;
#pragma unroll 1
        for (int kc = 0; kc < 128 / KC; kc++) {
            if (kc + 1 < 128 / KC) {
                copyB(s, kc + 1, buf ^ 1);
                asm volatile("cp.async.wait_group 1;");
            } else {
                asm volatile("cp.async.wait_group 0;");
            }
            __syncthreads();

            const float* B = sB[buf];
            const int kk0 = kc * KC;
#pragma unroll
            for (int ks = 0; ks < KC / 8; ks++) {
                uint32_t a[2][4], b[8][2];
#pragma unroll
                for (int mt = 0; mt < 2; mt++) {
                    int r = wm + mt * 16 + gid;
                    int kk = kk0 + ks * 8 + tig;
                    float f0 = sA[r * ASTR + kk];
                    float f1 = sA[(r + 8) * ASTR + kk];
                    float f2 = sA[r * ASTR + kk + 4];
                    float f3 = sA[(r + 8) * ASTR + kk + 4];
                    asm("cvt.rna.tf32.f32 %0, %1;" : "=r"(a[mt][0]) : "f"(f0));
                    asm("cvt.rna.tf32.f32 %0, %1;" : "=r"(a[mt][1]) : "f"(f1));
                    asm("cvt.rna.tf32.f32 %0, %1;" : "=r"(a[mt][2]) : "f"(f2));
                    asm("cvt.rna.tf32.f32 %0, %1;" : "=r"(a[mt][3]) : "f"(f3));
                }
#pragma unroll
                for (int nt = 0; nt < 8; nt++) {
                    int col = wn + nt * 8 + gid;
                    b[nt][0] = __float_as_uint(B[(ks * 8 + tig) * BSTR + col]);
                    b[nt][1] = __float_as_uint(B[(ks * 8 + tig + 4) * BSTR + col]);
                }
#pragma unroll
                for (int mt = 0; mt < 2; mt++)
#pragma unroll
                    for (int nt = 0; nt < 8; nt++) MMA_TF32(c[mt][nt], a[mt], b[nt]);
            }
            buf ^= 1;
            __syncthreads();  // done reading old buf / sA chunk before reuse
        }
        // trailing __syncthreads above also protects sA before next gather
    }

    // ---- epilogue: ReLU + store ----
    float* O = out + (size_t)side * NUSERS * 128;
#pragma unroll
    for (int mt = 0; mt < 2; mt++) {
        int r0 = row0 + wm + mt * 16 + gid;
        int r1 = r0 + 8;
#pragma unroll
        for (int nt = 0; nt < 8; nt++) {
            int cg = wn + nt * 8 + tig * 2;
            if (r0 < NUSERS)
                *(float2*)&O[(size_t)r0 * 128 + cg] =
                    make_float2(fmaxf(c[mt][nt][0], 0.f), fmaxf(c[mt][nt][1], 0.f));
            if (r1 < NUSERS)
                *(float2*)&O[(size_t)r1 * 128 + cg] =
                    make_float2(fmaxf(c[mt][nt][2], 0.f), fmaxf(c[mt][nt][3], 0.f));
        }
    }
}

// ---------------------------------------------------------------------------
// kernel_launch
// ---------------------------------------------------------------------------
extern "C" void kernel_launch(void* const* d_in, const int* in_sizes, int n_in,
                              void* d_out, int out_size) {
    const float* U = (const float*)d_in[0];
    const float* It = (const float*)d_in[1];
    const float* W = (const float*)d_in[2];
    const int* u_rows = (const int*)d_in[3];
    const int* u_cols = (const int*)d_in[4];
    const float* u_vals = (const float*)d_in[5];
    const int* i_rows = (const int*)d_in[6];
    const int* i_cols = (const int*)d_in[7];
    const float* i_vals = (const float*)d_in[8];
    float* out = (float*)d_out;

    wcum_kernel<<<DIN, DOUT>>>(W);

    // --- CSR build ---
    zero_kernel<<<(NBINS + 255) / 256, 256>>>();
    const int eb = (NSUP * NEDGE + 255) / 256;
    hist_kernel<<<eb, 256>>>(u_rows, 0);
    hist_kernel<<<eb, 256>>>(i_rows, 1);
    scan1_kernel<<<NCHUNK, 256>>>();
    scan2_kernel<<<1, 1024>>>();
    scan3_kernel<<<NCHUNK, 256>>>();
    scatter_kernel<<<eb, 256>>>(u_rows, u_cols, u_vals, 0);
    scatter_kernel<<<eb, 256>>>(i_rows, i_cols, i_vals, 1);

    // --- fused gather + GEMM + ReLU ---
    dim3 g(MTILES, 2);
    fused_kernel<<<g, 256>>>(U, It, out);
}

// round 5
// speedup vs baseline: 1.4934x; 1.4934x over previous
#include <cuda_runtime.h>
#include <cstdint>
#include <cstddef>

#define NUSERS 100000
#define NITEMS 100000
#define DIN 128
#define DOUT 128
#define NSUP 5
#define NEDGE 500000
#define MTILES ((NUSERS + 127) / 128)
#define NBINS (2 * NSUP * NUSERS)          // 1,000,000 bins (side,s,row)
#define NCHUNK ((NBINS + 1023) / 1024)     // 977
#define TOTE (2 * NSUP * NEDGE)            // 5,000,000 edges

// ---------------------------------------------------------------------------
// Device scratch
// ---------------------------------------------------------------------------
__device__ float g_Wc[NSUP][DIN * DOUT];              // tf32-rounded cumulative W
__device__ float g_G[2][NSUP][(size_t)NUSERS * 128];  // 512 MB: A_s @ inputs
__device__ int g_cnt[NBINS];                          // histogram, then cursor
__device__ int g_off[NBINS + 1];                      // CSR offsets
__device__ int g_blksum[1024];                        // scan block sums
__device__ int2 g_edges[TOTE];                        // {col, val_bits} binned

// ---------------------------------------------------------------------------
// Cumulative weight, rounded to tf32.  weight layout [din][dout][s]
// ---------------------------------------------------------------------------
__global__ void wcum_kernel(const float* __restrict__ w) {
    int din = blockIdx.x;
    int dout = threadIdx.x;
    const float* p = w + ((size_t)din * DOUT + dout) * NSUP;
    float acc = 0.f;
#pragma unroll
    for (int s = 0; s < NSUP; s++) {
        acc += p[s];
        uint32_t r;
        asm("cvt.rna.tf32.f32 %0, %1;" : "=r"(r) : "f"(acc));
        g_Wc[s][din * DOUT + dout] = __uint_as_float(r);
    }
}

// ---------------------------------------------------------------------------
// CSR build: zero -> histogram -> scan(3) -> scatter (both sides per launch)
// bin = (side*NSUP + s)*NUSERS + row
// ---------------------------------------------------------------------------
__global__ void zero_kernel() {
    int i = blockIdx.x * 256 + threadIdx.x;
    if (i < NBINS) g_cnt[i] = 0;
}

__global__ void hist_kernel(const int* __restrict__ u_rows,
                            const int* __restrict__ i_rows) {
    int e = blockIdx.x * 256 + threadIdx.x;
    if (e >= TOTE) return;
    int side = (e >= NSUP * NEDGE) ? 1 : 0;
    int ee = e - side * NSUP * NEDGE;
    const int* rows = side ? i_rows : u_rows;
    int s = ee / NEDGE;
    int bin = (side * NSUP + s) * NUSERS + __ldg(&rows[ee]);
    atomicAdd(&g_cnt[bin], 1);
}

__global__ __launch_bounds__(256) void scan1_kernel() {
    __shared__ int s0[256], s1[256];
    int b = blockIdx.x, tid = threadIdx.x;
    int base = b * 1024 + tid * 4;
    int v[4];
#pragma unroll
    for (int j = 0; j < 4; j++) {
        int idx = base + j;
        v[j] = (idx < NBINS) ? g_cnt[idx] : 0;
    }
    int tsum = v[0] + v[1] + v[2] + v[3];
    s0[tid] = tsum;
    __syncthreads();
    int* src = s0;
    int* dst = s1;
#pragma unroll
    for (int o = 1; o < 256; o <<= 1) {
        int x = src[tid];
        if (tid >= o) x += src[tid - o];
        __syncthreads();
        dst[tid] = x;
        __syncthreads();
        int* tmp = src; src = dst; dst = tmp;
    }
    int run = (tid == 0) ? 0 : src[tid - 1];
#pragma unroll
    for (int j = 0; j < 4; j++) {
        int idx = base + j;
        if (idx < NBINS) g_off[idx] = run;
        run += v[j];
    }
    if (tid == 255) g_blksum[b] = src[255];
}

__global__ __launch_bounds__(1024) void scan2_kernel() {
    __shared__ int s0[1024], s1[1024];
    int tid = threadIdx.x;
    s0[tid] = (tid < NCHUNK) ? g_blksum[tid] : 0;
    __syncthreads();
    int* src = s0;
    int* dst = s1;
#pragma unroll
    for (int o = 1; o < 1024; o <<= 1) {
        int x = src[tid];
        if (tid >= o) x += src[tid - o];
        __syncthreads();
        dst[tid] = x;
        __syncthreads();
        int* tmp = src; src = dst; dst = tmp;
    }
    int excl = (tid == 0) ? 0 : src[tid - 1];
    if (tid < NCHUNK) g_blksum[tid] = excl;
    if (tid == 0) g_off[NBINS] = TOTE;
}

__global__ __launch_bounds__(256) void scan3_kernel() {
    int b = blockIdx.x;
    int add = g_blksum[b];
#pragma unroll
    for (int j = 0; j < 4; j++) {
        int idx = b * 1024 + threadIdx.x + 256 * j;
        if (idx < NBINS) {
            int o = g_off[idx] + add;
            g_off[idx] = o;
            g_cnt[idx] = o;  // cursor init
        }
    }
}

__global__ void scatter_kernel(const int* __restrict__ u_rows,
                               const int* __restrict__ u_cols,
                               const float* __restrict__ u_vals,
                               const int* __restrict__ i_rows,
                               const int* __restrict__ i_cols,
                               const float* __restrict__ i_vals) {
    int e = blockIdx.x * 256 + threadIdx.x;
    if (e >= TOTE) return;
    int side = (e >= NSUP * NEDGE) ? 1 : 0;
    int ee = e - side * NSUP * NEDGE;
    const int* rows = side ? i_rows : u_rows;
    const int* cols = side ? i_cols : u_cols;
    const float* vals = side ? i_vals : u_vals;
    int s = ee / NEDGE;
    int bin = (side * NSUP + s) * NUSERS + __ldg(&rows[ee]);
    int pos = atomicAdd(&g_cnt[bin], 1);
    g_edges[pos] = make_int2(__ldg(&cols[ee]), __float_as_int(__ldg(&vals[ee])));
}

// ---------------------------------------------------------------------------
// Atomic-free gather SpMM: one warp per (side,row), loops over 5 supports.
// Streamed data (__ldcs / __stcs) bypasses L2 persistence; input rows stay hot.
// ---------------------------------------------------------------------------
__global__ __launch_bounds__(256) void gather_kernel(const float* __restrict__ U,
                                                     const float* __restrict__ It) {
    int w = (int)((blockIdx.x * 256u + threadIdx.x) >> 5);
    if (w >= 2 * NUSERS) return;
    int lane = threadIdx.x & 31;
    int side = (w >= NUSERS) ? 1 : 0;
    int row = w - side * NUSERS;
    const float4* src = (const float4*)(side == 0 ? It : U);

#pragma unroll
    for (int s = 0; s < NSUP; s++) {
        int bin = (side * NSUP + s) * NUSERS + row;
        int e0 = __ldg(&g_off[bin]);
        int e1 = __ldg(&g_off[bin + 1]);
        float4 acc = make_float4(0.f, 0.f, 0.f, 0.f);
        int e = e0;
        for (; e + 2 <= e1; e += 2) {  // 2-way batched for MLP
            int2 p0 = __ldcs(&g_edges[e]);
            int2 p1 = __ldcs(&g_edges[e + 1]);
            float4 x0 = __ldg(&src[(size_t)p0.x * 32 + lane]);
            float4 x1 = __ldg(&src[(size_t)p1.x * 32 + lane]);
            float v0 = __int_as_float(p0.y);
            float v1 = __int_as_float(p1.y);
            acc.x += v0 * x0.x + v1 * x1.x;
            acc.y += v0 * x0.y + v1 * x1.y;
            acc.z += v0 * x0.z + v1 * x1.z;
            acc.w += v0 * x0.w + v1 * x1.w;
        }
        if (e < e1) {
            int2 p = __ldcs(&g_edges[e]);
            float v = __int_as_float(p.y);
            float4 x = __ldg(&src[(size_t)p.x * 32 + lane]);
            acc.x += v * x.x;
            acc.y += v * x.y;
            acc.z += v * x.z;
            acc.w += v * x.w;
        }
        __stcs((float4*)(g_G[side][s] + (size_t)row * 128) + lane, acc);
    }
}

// ---------------------------------------------------------------------------
// Tensor GEMM, K = 640:  out[side] = relu( [G_0|...|G_4] @ [Wc_0;...;Wc_4] )
// 256 thr / 8 warps (4m x 2n), block tile 128x128, warp tile 32x64.
// KC=16 double-buffered cp.async for both A and B.
// ---------------------------------------------------------------------------
#define KC 16
#define ASTR 20    // frag reads gid*20+tig mod 32 cover all banks
#define BSTR 136   // frag reads tig*8+gid cover all banks

__device__ __forceinline__ void cp16(float* sdst, const float* gsrc) {
    unsigned u = (unsigned)__cvta_generic_to_shared(sdst);
    asm volatile("cp.async.cg.shared.global [%0], [%1], 16;" :: "r"(u), "l"(gsrc));
}

#define MMA_TF32(c, a, b)                                                    \
    asm volatile(                                                            \
        "mma.sync.aligned.m16n8k8.row.col.f32.tf32.tf32.f32 "               \
        "{%0,%1,%2,%3}, {%4,%5,%6,%7}, {%8,%9}, {%0,%1,%2,%3};"             \
        : "+f"(c[0]), "+f"(c[1]), "+f"(c[2]), "+f"(c[3])                     \
        : "r"(a[0]), "r"(a[1]), "r"(a[2]), "r"(a[3]), "r"(b[0]), "r"(b[1]))

__global__ __launch_bounds__(256, 2) void gemm_kernel(float* __restrict__ out) {
    const int side = blockIdx.y;
    const int row0 = blockIdx.x * 128;

    __shared__ float sA[2][128 * ASTR];  // 20.5 KB
    __shared__ float sB[2][KC * BSTR];   // 17.4 KB

    const int t = threadIdx.x;
    const int wid = t >> 5;
    const int lane = t & 31;
    const int gid = lane >> 2;  // 0..7
    const int tig = lane & 3;   // 0..3
    const int wm = (wid & 3) * 32;
    const int wn = (wid >> 2) * 64;

    float c[2][8][4];
#pragma unroll
    for (int mt = 0; mt < 2; mt++)
#pragma unroll
        for (int nt = 0; nt < 8; nt++)
#pragma unroll
            for (int i = 0; i < 4; i++) c[mt][nt][i] = 0.f;

    auto copy_chunk = [&](int kc, int b) {
        const float* Asrc = g_G[side][kc >> 3];
        const float* Bsrc = g_Wc[kc >> 3];
        const int kk0 = (kc & 7) * 16;
        // A: 128 rows x 16 floats = 512 quads, 2 per thread
#pragma unroll
        for (int i = 0; i < 2; i++) {
            int q = t + 256 * i;
            int row = q >> 2, c4 = (q & 3) * 4;
            int gr = row0 + row;
            if (gr > NUSERS - 1) gr = NUSERS - 1;  // clamp; stores guarded
            cp16(&sA[b][row * ASTR + c4], Asrc + (size_t)gr * 128 + kk0 + c4);
        }
        // B: 16 k-rows x 128 floats = 512 quads
#pragma unroll
        for (int i = 0; i < 2; i++) {
            int q = t + 256 * i;
            int kr = q >> 5, c4 = (q & 31) * 4;
            cp16(&sB[b][kr * BSTR + c4], Bsrc + (size_t)(kk0 + kr) * 128 + c4);
        }
        asm volatile("cp.async.commit_group;");
    };

    copy_chunk(0, 0);
    int buf = 0;

#pragma unroll 1
    for (int kc = 0; kc < 640 / KC; kc++) {
        if (kc + 1 < 640 / KC) {
            copy_chunk(kc + 1, buf ^ 1);
            asm volatile("cp.async.wait_group 1;");
        } else {
            asm volatile("cp.async.wait_group 0;");
        }
        __syncthreads();

        const float* A = sA[buf];
        const float* B = sB[buf];
#pragma unroll
        for (int ks = 0; ks < KC / 8; ks++) {
            uint32_t a[2][4], b[8][2];
#pragma unroll
            for (int mt = 0; mt < 2; mt++) {
                int r = wm + mt * 16 + gid;
                int kk = ks * 8 + tig;
                float f0 = A[r * ASTR + kk];
                float f1 = A[(r + 8) * ASTR + kk];
                float f2 = A[r * ASTR + kk + 4];
                float f3 = A[(r + 8) * ASTR + kk + 4];
                asm("cvt.rna.tf32.f32 %0, %1;" : "=r"(a[mt][0]) : "f"(f0));
                asm("cvt.rna.tf32.f32 %0, %1;" : "=r"(a[mt][1]) : "f"(f1));
                asm("cvt.rna.tf32.f32 %0, %1;" : "=r"(a[mt][2]) : "f"(f2));
                asm("cvt.rna.tf32.f32 %0, %1;" : "=r"(a[mt][3]) : "f"(f3));
            }
#pragma unroll
            for (int nt = 0; nt < 8; nt++) {
                int col = wn + nt * 8 + gid;
                b[nt][0] = __float_as_uint(B[(ks * 8 + tig) * BSTR + col]);
                b[nt][1] = __float_as_uint(B[(ks * 8 + tig + 4) * BSTR + col]);
            }
#pragma unroll
            for (int mt = 0; mt < 2; mt++)
#pragma unroll
                for (int nt = 0; nt < 8; nt++) MMA_TF32(c[mt][nt], a[mt], b[nt]);
        }
        buf ^= 1;
        __syncthreads();
    }

    float* O = out + (size_t)side * NUSERS * 128;
#pragma unroll
    for (int mt = 0; mt < 2; mt++) {
        int r0 = row0 + wm + mt * 16 + gid;
        int r1 = r0 + 8;
#pragma unroll
        for (int nt = 0; nt < 8; nt++) {
            int cg = wn + nt * 8 + tig * 2;
            if (r0 < NUSERS)
                *(float2*)&O[(size_t)r0 * 128 + cg] =
                    make_float2(fmaxf(c[mt][nt][0], 0.f), fmaxf(c[mt][nt][1], 0.f));
            if (r1 < NUSERS)
                *(float2*)&O[(size_t)r1 * 128 + cg] =
                    make_float2(fmaxf(c[mt][nt][2], 0.f), fmaxf(c[mt][nt][3], 0.f));
        }
    }
}

// ---------------------------------------------------------------------------
// kernel_launch
// ---------------------------------------------------------------------------
extern "C" void kernel_launch(void* const* d_in, const int* in_sizes, int n_in,
                              void* d_out, int out_size) {
    const float* U = (const float*)d_in[0];
    const float* It = (const float*)d_in[1];
    const float* W = (const float*)d_in[2];
    const int* u_rows = (const int*)d_in[3];
    const int* u_cols = (const int*)d_in[4];
    const float* u_vals = (const float*)d_in[5];
    const int* i_rows = (const int*)d_in[6];
    const int* i_cols = (const int*)d_in[7];
    const float* i_vals = (const float*)d_in[8];
    float* out = (float*)d_out;

    wcum_kernel<<<DIN, DOUT>>>(W);

    // --- CSR build ---
    zero_kernel<<<(NBINS + 255) / 256, 256>>>();
    const int eb = (TOTE + 255) / 256;
    hist_kernel<<<eb, 256>>>(u_rows, i_rows);
    scan1_kernel<<<NCHUNK, 256>>>();
    scan2_kernel<<<1, 1024>>>();
    scan3_kernel<<<NCHUNK, 256>>>();
    scatter_kernel<<<eb, 256>>>(u_rows, u_cols, u_vals, i_rows, i_cols, i_vals);

    // --- atomic-free SpMM of raw inputs ---
    gather_kernel<<<(2 * NUSERS * 32 + 255) / 256, 256>>>(U, It);

    // --- K=640 GEMM + fused ReLU ---
    dim3 g(MTILES, 2);
    gemm_kernel<<<g, 256>>>(out);
}

// round 6
// speedup vs baseline: 1.9751x; 1.3225x over previous
#include <cuda_runtime.h>
#include <cuda_fp16.h>
#include <cstdint>
#include <cstddef>

#define NUSERS 100000
#define NITEMS 100000
#define DIN 128
#define DOUT 128
#define NSUP 5
#define NEDGE 500000
#define MTILES ((NUSERS + 127) / 128)
#define NBINS (2 * NSUP * NUSERS)          // 1,000,000 bins (side,s,row)
#define NCHUNK ((NBINS + 1023) / 1024)     // 977
#define TOTE (2 * NSUP * NEDGE)            // 5,000,000 edges

// ---------------------------------------------------------------------------
// Device scratch
// ---------------------------------------------------------------------------
__device__ __half2 g_Wh[NSUP][64 * DOUT];              // interleaved (k,k+1) pairs
__device__ __half g_Uh[(size_t)NUSERS * 128];          // fp16 user inputs
__device__ __half g_Ih[(size_t)NITEMS * 128];          // fp16 item inputs
__device__ __half g_Gh[2][NSUP][(size_t)NUSERS * 128]; // 256 MB gathered A
__device__ int g_cnt[NBINS];
__device__ int g_off[NBINS + 1];
__device__ int g_blksum[1024];
__device__ int2 g_edges[TOTE];

// ---------------------------------------------------------------------------
// Cumulative weight -> fp16, interleaved half2 (k even, k odd) per dout col.
// weight layout [din][dout][s];  g_Wh[s][kp*128 + n] = (Wc[2kp][n], Wc[2kp+1][n])
// ---------------------------------------------------------------------------
__global__ void wcum_kernel(const float* __restrict__ w) {
    int kp = blockIdx.x;   // 0..63
    int n = threadIdx.x;   // 0..127
    const float* p0 = w + ((size_t)(2 * kp) * DOUT + n) * NSUP;
    const float* p1 = w + ((size_t)(2 * kp + 1) * DOUT + n) * NSUP;
    float a0 = 0.f, a1 = 0.f;
#pragma unroll
    for (int s = 0; s < NSUP; s++) {
        a0 += p0[s];
        a1 += p1[s];
        g_Wh[s][kp * 128 + n] = __floats2half2_rn(a0, a1);
    }
}

// ---------------------------------------------------------------------------
// Convert fp32 inputs to fp16 (both sides).
// ---------------------------------------------------------------------------
__global__ void cvt_kernel(const float* __restrict__ U, const float* __restrict__ It) {
    const int per = NUSERS * 128 / 4;  // float4 units per side
    int i = blockIdx.x * 256 + threadIdx.x;
    if (i >= 2 * per) return;
    int side = (i >= per) ? 1 : 0;
    int j = i - side * per;
    float4 v = __ldcs((const float4*)(side ? It : U) + j);
    __half* dst = side ? g_Ih : g_Uh;
    uint2 o;
    __half2 h0 = __floats2half2_rn(v.x, v.y);
    __half2 h1 = __floats2half2_rn(v.z, v.w);
    o.x = *(uint32_t*)&h0;
    o.y = *(uint32_t*)&h1;
    __stcs((uint2*)dst + j, o);
}

// ---------------------------------------------------------------------------
// CSR build: zero -> histogram -> scan(3) -> scatter
// ---------------------------------------------------------------------------
__global__ void zero_kernel() {
    int i = blockIdx.x * 256 + threadIdx.x;
    if (i < NBINS) g_cnt[i] = 0;
}

__global__ void hist_kernel(const int* __restrict__ u_rows,
                            const int* __restrict__ i_rows) {
    int e = blockIdx.x * 256 + threadIdx.x;
    if (e >= TOTE) return;
    int side = (e >= NSUP * NEDGE) ? 1 : 0;
    int ee = e - side * NSUP * NEDGE;
    const int* rows = side ? i_rows : u_rows;
    int s = ee / NEDGE;
    int bin = (side * NSUP + s) * NUSERS + __ldg(&rows[ee]);
    atomicAdd(&g_cnt[bin], 1);
}

__global__ __launch_bounds__(256) void scan1_kernel() {
    __shared__ int s0[256], s1[256];
    int b = blockIdx.x, tid = threadIdx.x;
    int base = b * 1024 + tid * 4;
    int v[4];
#pragma unroll
    for (int j = 0; j < 4; j++) {
        int idx = base + j;
        v[j] = (idx < NBINS) ? g_cnt[idx] : 0;
    }
    int tsum = v[0] + v[1] + v[2] + v[3];
    s0[tid] = tsum;
    __syncthreads();
    int* src = s0;
    int* dst = s1;
#pragma unroll
    for (int o = 1; o < 256; o <<= 1) {
        int x = src[tid];
        if (tid >= o) x += src[tid - o];
        __syncthreads();
        dst[tid] = x;
        __syncthreads();
        int* tmp = src; src = dst; dst = tmp;
    }
    int run = (tid == 0) ? 0 : src[tid - 1];
#pragma unroll
    for (int j = 0; j < 4; j++) {
        int idx = base + j;
        if (idx < NBINS) g_off[idx] = run;
        run += v[j];
    }
    if (tid == 255) g_blksum[b] = src[255];
}

__global__ __launch_bounds__(1024) void scan2_kernel() {
    __shared__ int s0[1024], s1[1024];
    int tid = threadIdx.x;
    s0[tid] = (tid < NCHUNK) ? g_blksum[tid] : 0;
    __syncthreads();
    int* src = s0;
    int* dst = s1;
#pragma unroll
    for (int o = 1; o < 1024; o <<= 1) {
        int x = src[tid];
        if (tid >= o) x += src[tid - o];
        __syncthreads();
        dst[tid] = x;
        __syncthreads();
        int* tmp = src; src = dst; dst = tmp;
    }
    int excl = (tid == 0) ? 0 : src[tid - 1];
    if (tid < NCHUNK) g_blksum[tid] = excl;
    if (tid == 0) g_off[NBINS] = TOTE;
}

__global__ __launch_bounds__(256) void scan3_kernel() {
    int b = blockIdx.x;
    int add = g_blksum[b];
#pragma unroll
    for (int j = 0; j < 4; j++) {
        int idx = b * 1024 + threadIdx.x + 256 * j;
        if (idx < NBINS) {
            int o = g_off[idx] + add;
            g_off[idx] = o;
            g_cnt[idx] = o;
        }
    }
}

__global__ void scatter_kernel(const int* __restrict__ u_rows,
                               const int* __restrict__ u_cols,
                               const float* __restrict__ u_vals,
                               const int* __restrict__ i_rows,
                               const int* __restrict__ i_cols,
                               const float* __restrict__ i_vals) {
    int e = blockIdx.x * 256 + threadIdx.x;
    if (e >= TOTE) return;
    int side = (e >= NSUP * NEDGE) ? 1 : 0;
    int ee = e - side * NSUP * NEDGE;
    const int* rows = side ? i_rows : u_rows;
    const int* cols = side ? i_cols : u_cols;
    const float* vals = side ? i_vals : u_vals;
    int s = ee / NEDGE;
    int bin = (side * NSUP + s) * NUSERS + __ldg(&rows[ee]);
    int pos = atomicAdd(&g_cnt[bin], 1);
    g_edges[pos] = make_int2(__ldg(&cols[ee]), __float_as_int(__ldg(&vals[ee])));
}

// ---------------------------------------------------------------------------
// Atomic-free gather SpMM (fp16 rows, fp32 accumulate): warp per (side,row).
// Each lane covers 4 halves (8 B): whole 256 B row per warp.
// ---------------------------------------------------------------------------
__global__ __launch_bounds__(256) void gather_kernel() {
    int w = (int)((blockIdx.x * 256u + threadIdx.x) >> 5);
    if (w >= 2 * NUSERS) return;
    int lane = threadIdx.x & 31;
    int side = (w >= NUSERS) ? 1 : 0;
    int row = w - side * NUSERS;
    const uint2* src = (const uint2*)(side == 0 ? g_Ih : g_Uh);

#pragma unroll
    for (int s = 0; s < NSUP; s++) {
        int bin = (side * NSUP + s) * NUSERS + row;
        int e0 = __ldg(&g_off[bin]);
        int e1 = __ldg(&g_off[bin + 1]);
        float4 acc = make_float4(0.f, 0.f, 0.f, 0.f);
        int e = e0;
        for (; e + 2 <= e1; e += 2) {
            int2 p0 = __ldcs(&g_edges[e]);
            int2 p1 = __ldcs(&g_edges[e + 1]);
            uint2 x0 = __ldg(&src[(size_t)p0.x * 32 + lane]);
            uint2 x1 = __ldg(&src[(size_t)p1.x * 32 + lane]);
            float v0 = __int_as_float(p0.y);
            float v1 = __int_as_float(p1.y);
            float2 a0 = __half22float2(*(__half2*)&x0.x);
            float2 b0 = __half22float2(*(__half2*)&x0.y);
            float2 a1 = __half22float2(*(__half2*)&x1.x);
            float2 b1 = __half22float2(*(__half2*)&x1.y);
            acc.x += v0 * a0.x + v1 * a1.x;
            acc.y += v0 * a0.y + v1 * a1.y;
            acc.z += v0 * b0.x + v1 * b1.x;
            acc.w += v0 * b0.y + v1 * b1.y;
        }
        if (e < e1) {
            int2 p = __ldcs(&g_edges[e]);
            float v = __int_as_float(p.y);
            uint2 x = __ldg(&src[(size_t)p.x * 32 + lane]);
            float2 a = __half22float2(*(__half2*)&x.x);
            float2 b = __half22float2(*(__half2*)&x.y);
            acc.x += v * a.x;
            acc.y += v * a.y;
            acc.z += v * b.x;
            acc.w += v * b.y;
        }
        __half2 o0 = __floats2half2_rn(acc.x, acc.y);
        __half2 o1 = __floats2half2_rn(acc.z, acc.w);
        uint2 o;
        o.x = *(uint32_t*)&o0;
        o.y = *(uint32_t*)&o1;
        __stcs((uint2*)(g_Gh[side][s] + (size_t)row * 128) + lane, o);
    }
}

// ---------------------------------------------------------------------------
// fp16 tensor GEMM, K = 640:  out[side] = relu( [G_0|..|G_4] @ [Wc_0;..;Wc_4] )
// 256 thr / 8 warps (4m x 2n), block tile 128x128, warp tile 32x64.
// mma.sync m16n8k16 f16->f32.  KC = 32 halves, double-buffered cp.async.
// ---------------------------------------------------------------------------
#define KC 32
#define AST2 20    // A row stride in 32-bit words (40 halves)
#define BST2 136   // B row stride in 32-bit words (half2 cols)

__device__ __forceinline__ void cp16(void* sdst, const void* gsrc) {
    unsigned u = (unsigned)__cvta_generic_to_shared(sdst);
    asm volatile("cp.async.cg.shared.global [%0], [%1], 16;" :: "r"(u), "l"(gsrc));
}

#define MMA_F16(c, a, b)                                                     \
    asm volatile(                                                            \
        "mma.sync.aligned.m16n8k16.row.col.f32.f16.f16.f32 "                \
        "{%0,%1,%2,%3}, {%4,%5,%6,%7}, {%8,%9}, {%0,%1,%2,%3};"             \
        : "+f"(c[0]), "+f"(c[1]), "+f"(c[2]), "+f"(c[3])                     \
        : "r"(a[0]), "r"(a[1]), "r"(a[2]), "r"(a[3]), "r"(b[0]), "r"(b[1]))

__global__ __launch_bounds__(256, 2) void gemm_kernel(float* __restrict__ out) {
    const int side = blockIdx.y;
    const int row0 = blockIdx.x * 128;

    __shared__ uint32_t sA[2][128 * AST2];  // 20.5 KB
    __shared__ uint32_t sB[2][16 * BST2];   // 17.4 KB

    const int t = threadIdx.x;
    const int wid = t >> 5;
    const int lane = t & 31;
    const int gid = lane >> 2;
    const int tig = lane & 3;
    const int wm = (wid & 3) * 32;
    const int wn = (wid >> 2) * 64;

    float c[2][8][4];
#pragma unroll
    for (int mt = 0; mt < 2; mt++)
#pragma unroll
        for (int nt = 0; nt < 8; nt++)
#pragma unroll
            for (int i = 0; i < 4; i++) c[mt][nt][i] = 0.f;

    // one chunk = 32 halves of K
    auto copy_chunk = [&](int kc, int b) {
        const int s = kc >> 2;
        const int kk0 = (kc & 3) * 32;      // half offset within the 128-col row
        const __half* Asrc = g_Gh[side][s];
        // A: 128 rows x 32 halves = 512 16B-quads, 2 per thread
#pragma unroll
        for (int i = 0; i < 2; i++) {
            int q = t + 256 * i;
            int row = q >> 2, c8 = (q & 3) * 8;  // 8 halves per quad
            int gr = row0 + row;
            if (gr > NUSERS - 1) gr = NUSERS - 1;
            cp16((char*)&sA[b][row * AST2] + c8 * 2,
                 Asrc + (size_t)gr * 128 + kk0 + c8);
        }
        // B: 16 kp-rows x 128 half2 words = 512 quads, 2 per thread
        const __half2* Bsrc = g_Wh[s] + (kk0 >> 1) * 128;
#pragma unroll
        for (int i = 0; i < 2; i++) {
            int q = t + 256 * i;
            int kr = q >> 5, c4 = (q & 31) * 4;
            cp16(&sB[b][kr * BST2 + c4], Bsrc + (size_t)kr * 128 + c4);
        }
        asm volatile("cp.async.commit_group;");
    };

    copy_chunk(0, 0);
    int buf = 0;

#pragma unroll 1
    for (int kc = 0; kc < 640 / KC; kc++) {
        if (kc + 1 < 640 / KC) {
            copy_chunk(kc + 1, buf ^ 1);
            asm volatile("cp.async.wait_group 1;");
        } else {
            asm volatile("cp.async.wait_group 0;");
        }
        __syncthreads();

        const uint32_t* A = sA[buf];
        const uint32_t* B = sB[buf];
#pragma unroll
        for (int ks = 0; ks < 2; ks++) {   // two k16 steps per 32-half chunk
            uint32_t a[2][4], b[8][2];
#pragma unroll
            for (int mt = 0; mt < 2; mt++) {
                int r = wm + mt * 16 + gid;
                int cw = ks * 8 + tig;
                a[mt][0] = A[r * AST2 + cw];
                a[mt][1] = A[(r + 8) * AST2 + cw];
                a[mt][2] = A[r * AST2 + cw + 4];
                a[mt][3] = A[(r + 8) * AST2 + cw + 4];
            }
#pragma unroll
            for (int nt = 0; nt < 8; nt++) {
                int col = wn + nt * 8 + gid;
                b[nt][0] = B[(ks * 8 + tig) * BST2 + col];
                b[nt][1] = B[(ks * 8 + tig + 4) * BST2 + col];
            }
#pragma unroll
            for (int mt = 0; mt < 2; mt++)
#pragma unroll
                for (int nt = 0; nt < 8; nt++) MMA_F16(c[mt][nt], a[mt], b[nt]);
        }
        buf ^= 1;
        __syncthreads();
    }

    float* O = out + (size_t)side * NUSERS * 128;
#pragma unroll
    for (int mt = 0; mt < 2; mt++) {
        int r0 = row0 + wm + mt * 16 + gid;
        int r1 = r0 + 8;
#pragma unroll
        for (int nt = 0; nt < 8; nt++) {
            int cg = wn + nt * 8 + tig * 2;
            if (r0 < NUSERS)
                *(float2*)&O[(size_t)r0 * 128 + cg] =
                    make_float2(fmaxf(c[mt][nt][0], 0.f), fmaxf(c[mt][nt][1], 0.f));
            if (r1 < NUSERS)
                *(float2*)&O[(size_t)r1 * 128 + cg] =
                    make_float2(fmaxf(c[mt][nt][2], 0.f), fmaxf(c[mt][nt][3], 0.f));
        }
    }
}

// ---------------------------------------------------------------------------
// kernel_launch
// ---------------------------------------------------------------------------
extern "C" void kernel_launch(void* const* d_in, const int* in_sizes, int n_in,
                              void* d_out, int out_size) {
    const float* U = (const float*)d_in[0];
    const float* It = (const float*)d_in[1];
    const float* W = (const float*)d_in[2];
    const int* u_rows = (const int*)d_in[3];
    const int* u_cols = (const int*)d_in[4];
    const float* u_vals = (const float*)d_in[5];
    const int* i_rows = (const int*)d_in[6];
    const int* i_cols = (const int*)d_in[7];
    const float* i_vals = (const float*)d_in[8];
    float* out = (float*)d_out;

    wcum_kernel<<<64, 128>>>(W);
    cvt_kernel<<<(2 * NUSERS * 128 / 4 + 255) / 256, 256>>>(U, It);

    // --- CSR build ---
    zero_kernel<<<(NBINS + 255) / 256, 256>>>();
    const int eb = (TOTE + 255) / 256;
    hist_kernel<<<eb, 256>>>(u_rows, i_rows);
    scan1_kernel<<<NCHUNK, 256>>>();
    scan2_kernel<<<1, 1024>>>();
    scan3_kernel<<<NCHUNK, 256>>>();
    scatter_kernel<<<eb, 256>>>(u_rows, u_cols, u_vals, i_rows, i_cols, i_vals);

    // --- atomic-free fp16 gather SpMM ---
    gather_kernel<<<(2 * NUSERS * 32 + 255) / 256, 256>>>();

    // --- fp16 K=640 GEMM + fused ReLU ---
    dim3 g(MTILES, 2);
    gemm_kernel<<<g, 256>>>(out);
}

// round 8
// speedup vs baseline: 2.0305x; 1.0280x over previous
#include <cuda_runtime.h>
#include <cuda_fp16.h>
#include <cstdint>
#include <cstddef>

#define NUSERS 100000
#define NITEMS 100000
#define DIN 128
#define DOUT 128
#define NSUP 5
#define NEDGE 500000
#define MTILES ((NUSERS + 127) / 128)
#define NBINS (2 * NSUP * NUSERS)
#define NCHUNK ((NBINS + 1023) / 1024)
#define TOTE (2 * NSUP * NEDGE)

// ---------------------------------------------------------------------------
// Device scratch
// ---------------------------------------------------------------------------
__device__ __half g_Wn[NSUP][DOUT * DIN];              // n-major: [s][n*128 + k]
__device__ __half g_Uh[(size_t)NUSERS * 128];
__device__ __half g_Ih[(size_t)NITEMS * 128];
__device__ __half g_Gh[2][NSUP][(size_t)NUSERS * 128]; // 256 MB gathered A
__device__ int g_cnt[NBINS];
__device__ int g_off[NBINS + 1];
__device__ int g_blksum[1024];
__device__ int2 g_edges[TOTE];

// ---------------------------------------------------------------------------
// Cumulative weight -> fp16, n-major (B^T row-major for .col operand).
// weight layout [k][n][s]
// ---------------------------------------------------------------------------
__global__ void wcum_kernel(const float* __restrict__ w) {
    int k = blockIdx.x;   // 0..127
    int n = threadIdx.x;  // 0..127
    const float* p = w + ((size_t)k * DOUT + n) * NSUP;
    float acc = 0.f;
#pragma unroll
    for (int s = 0; s < NSUP; s++) {
        acc += p[s];
        g_Wn[s][n * DIN + k] = __float2half_rn(acc);
    }
}

// ---------------------------------------------------------------------------
// Convert fp32 inputs to fp16.
// ---------------------------------------------------------------------------
__global__ void cvt_kernel(const float* __restrict__ U, const float* __restrict__ It) {
    const int per = NUSERS * 128 / 4;
    int i = blockIdx.x * 256 + threadIdx.x;
    if (i >= 2 * per) return;
    int side = (i >= per) ? 1 : 0;
    int j = i - side * per;
    float4 v = __ldcs((const float4*)(side ? It : U) + j);
    __half* dst = side ? g_Ih : g_Uh;
    uint2 o;
    __half2 h0 = __floats2half2_rn(v.x, v.y);
    __half2 h1 = __floats2half2_rn(v.z, v.w);
    o.x = *(uint32_t*)&h0;
    o.y = *(uint32_t*)&h1;
    __stcs((uint2*)dst + j, o);
}

// ---------------------------------------------------------------------------
// CSR build: zero -> histogram -> scan(3) -> scatter
// ---------------------------------------------------------------------------
__global__ void zero_kernel() {
    int i = blockIdx.x * 256 + threadIdx.x;
    if (i < NBINS) g_cnt[i] = 0;
}

__global__ void hist_kernel(const int* __restrict__ u_rows,
                            const int* __restrict__ i_rows) {
    int e = blockIdx.x * 256 + threadIdx.x;
    if (e >= TOTE) return;
    int side = (e >= NSUP * NEDGE) ? 1 : 0;
    int ee = e - side * NSUP * NEDGE;
    const int* rows = side ? i_rows : u_rows;
    int s = ee / NEDGE;
    int bin = (side * NSUP + s) * NUSERS + __ldg(&rows[ee]);
    atomicAdd(&g_cnt[bin], 1);
}

__global__ __launch_bounds__(256) void scan1_kernel() {
    __shared__ int s0[256], s1[256];
    int b = blockIdx.x, tid = threadIdx.x;
    int base = b * 1024 + tid * 4;
    int v[4];
#pragma unroll
    for (int j = 0; j < 4; j++) {
        int idx = base + j;
        v[j] = (idx < NBINS) ? g_cnt[idx] : 0;
    }
    int tsum = v[0] + v[1] + v[2] + v[3];
    s0[tid] = tsum;
    __syncthreads();
    int* src = s0;
    int* dst = s1;
#pragma unroll
    for (int o = 1; o < 256; o <<= 1) {
        int x = src[tid];
        if (tid >= o) x += src[tid - o];
        __syncthreads();
        dst[tid] = x;
        __syncthreads();
        int* tmp = src; src = dst; dst = tmp;
    }
    int run = (tid == 0) ? 0 : src[tid - 1];
#pragma unroll
    for (int j = 0; j < 4; j++) {
        int idx = base + j;
        if (idx < NBINS) g_off[idx] = run;
        run += v[j];
    }
    if (tid == 255) g_blksum[b] = src[255];
}

__global__ __launch_bounds__(1024) void scan2_kernel() {
    __shared__ int s0[1024], s1[1024];
    int tid = threadIdx.x;
    s0[tid] = (tid < NCHUNK) ? g_blksum[tid] : 0;
    __syncthreads();
    int* src = s0;
    int* dst = s1;
#pragma unroll
    for (int o = 1; o < 1024; o <<= 1) {
        int x = src[tid];
        if (tid >= o) x += src[tid - o];
        __syncthreads();
        dst[tid] = x;
        __syncthreads();
        int* tmp = src; src = dst; dst = tmp;
    }
    int excl = (tid == 0) ? 0 : src[tid - 1];
    if (tid < NCHUNK) g_blksum[tid] = excl;
    if (tid == 0) g_off[NBINS] = TOTE;
}

__global__ __launch_bounds__(256) void scan3_kernel() {
    int b = blockIdx.x;
    int add = g_blksum[b];
#pragma unroll
    for (int j = 0; j < 4; j++) {
        int idx = b * 1024 + threadIdx.x + 256 * j;
        if (idx < NBINS) {
            int o = g_off[idx] + add;
            g_off[idx] = o;
            g_cnt[idx] = o;
        }
    }
}

__global__ void scatter_kernel(const int* __restrict__ u_rows,
                               const int* __restrict__ u_cols,
                               const float* __restrict__ u_vals,
                               const int* __restrict__ i_rows,
                               const int* __restrict__ i_cols,
                               const float* __restrict__ i_vals) {
    int e = blockIdx.x * 256 + threadIdx.x;
    if (e >= TOTE) return;
    int side = (e >= NSUP * NEDGE) ? 1 : 0;
    int ee = e - side * NSUP * NEDGE;
    const int* rows = side ? i_rows : u_rows;
    const int* cols = side ? i_cols : u_cols;
    const float* vals = side ? i_vals : u_vals;
    int s = ee / NEDGE;
    int bin = (side * NSUP + s) * NUSERS + __ldg(&rows[ee]);
    int pos = atomicAdd(&g_cnt[bin], 1);
    g_edges[pos] = make_int2(__ldg(&cols[ee]), __float_as_int(__ldg(&vals[ee])));
}

// ---------------------------------------------------------------------------
// Atomic-free gather SpMM (fp16 rows, fp32 accumulate): warp per (side,row).
// ---------------------------------------------------------------------------
__global__ __launch_bounds__(256) void gather_kernel() {
    int w = (int)((blockIdx.x * 256u + threadIdx.x) >> 5);
    if (w >= 2 * NUSERS) return;
    int lane = threadIdx.x & 31;
    int side = (w >= NUSERS) ? 1 : 0;
    int row = w - side * NUSERS;
    const uint2* src = (const uint2*)(side == 0 ? g_Ih : g_Uh);

#pragma unroll
    for (int s = 0; s < NSUP; s++) {
        int bin = (side * NSUP + s) * NUSERS + row;
        int e0 = __ldg(&g_off[bin]);
        int e1 = __ldg(&g_off[bin + 1]);
        float4 acc = make_float4(0.f, 0.f, 0.f, 0.f);
        int e = e0;
        for (; e + 2 <= e1; e += 2) {
            int2 p0 = __ldcs(&g_edges[e]);
            int2 p1 = __ldcs(&g_edges[e + 1]);
            uint2 x0 = __ldg(&src[(size_t)p0.x * 32 + lane]);
            uint2 x1 = __ldg(&src[(size_t)p1.x * 32 + lane]);
            float v0 = __int_as_float(p0.y);
            float v1 = __int_as_float(p1.y);
            float2 a0 = __half22float2(*(__half2*)&x0.x);
            float2 b0 = __half22float2(*(__half2*)&x0.y);
            float2 a1 = __half22float2(*(__half2*)&x1.x);
            float2 b1 = __half22float2(*(__half2*)&x1.y);
            acc.x += v0 * a0.x + v1 * a1.x;
            acc.y += v0 * a0.y + v1 * a1.y;
            acc.z += v0 * b0.x + v1 * b1.x;
            acc.w += v0 * b0.y + v1 * b1.y;
        }
        if (e < e1) {
            int2 p = __ldcs(&g_edges[e]);
            float v = __int_as_float(p.y);
            uint2 x = __ldg(&src[(size_t)p.x * 32 + lane]);
            float2 a = __half22float2(*(__half2*)&x.x);
            float2 b = __half22float2(*(__half2*)&x.y);
            acc.x += v * a.x;
            acc.y += v * a.y;
            acc.z += v * b.x;
            acc.w += v * b.y;
        }
        __half2 o0 = __floats2half2_rn(acc.x, acc.y);
        __half2 o1 = __floats2half2_rn(acc.z, acc.w);
        uint2 o;
        o.x = *(uint32_t*)&o0;
        o.y = *(uint32_t*)&o1;
        __stcs((uint2*)(g_Gh[side][s] + (size_t)row * 128) + lane, o);
    }
}

// ---------------------------------------------------------------------------
// fp16 tensor GEMM, K = 640, ldmatrix-based fragment loads.
// 256 thr / 8 warps (4m x 2n), tile 128x128, warp tile 32x64.
// K chunked at 64 halves, double-buffered cp.async.
// smem rows: 64 halves + 8 pad = 144B stride (conflict-free LDSM phases).
// ---------------------------------------------------------------------------
#define RSTR 144                         // bytes per smem row
#define BUFB (128 * RSTR)                // 18432 B per operand-buffer
#define GT_TOTAL (4 * BUFB)              // 73728 B
#define NCHUNKS 10

__device__ __forceinline__ uint32_t smem_u32(const void* p) {
    uint32_t a;
    asm("{ .reg .u64 t; cvta.to.shared.u64 t, %1; cvt.u32.u64 %0, t; }" : "=r"(a) : "l"(p));
    return a;
}
__device__ __forceinline__ void cp16(void* sdst, const void* gsrc) {
    unsigned u = (unsigned)__cvta_generic_to_shared(sdst);
    asm volatile("cp.async.cg.shared.global [%0], [%1], 16;" :: "r"(u), "l"(gsrc));
}
#define LDSM_X4(r, addr)                                                       \
    asm volatile("ldmatrix.sync.aligned.m8n8.x4.shared.b16 {%0,%1,%2,%3}, [%4];" \
                 : "=r"((r)[0]), "=r"((r)[1]), "=r"((r)[2]), "=r"((r)[3])       \
                 : "r"(addr))
#define MMA_F16(c, a, b0, b1)                                                  \
    asm volatile(                                                              \
        "mma.sync.aligned.m16n8k16.row.col.f32.f16.f16.f32 "                  \
        "{%0,%1,%2,%3}, {%4,%5,%6,%7}, {%8,%9}, {%0,%1,%2,%3};"               \
        : "+f"(c[0]), "+f"(c[1]), "+f"(c[2]), "+f"(c[3])                       \
        : "r"(a[0]), "r"(a[1]), "r"(a[2]), "r"(a[3]), "r"(b0), "r"(b1))

__global__ __launch_bounds__(256, 2) void gemm_kernel(float* __restrict__ out) {
    extern __shared__ __align__(16) char smem[];
    const int side = blockIdx.y;
    const int row0 = blockIdx.x * 128;
    const uint32_t sb = smem_u32(smem);

    const int t = threadIdx.x;
    const int wid = t >> 5;
    const int lane = t & 31;
    const int gid = lane >> 2;
    const int tig = lane & 3;
    const int wm = (wid & 3) * 32;
    const int wn = (wid >> 2) * 64;

    // ldmatrix per-lane address components (bytes)
    const uint32_t aRowByte = (uint32_t)(wm + (lane & 15)) * RSTR + (lane >> 4) * 16;
    const uint32_t bRowByte = (uint32_t)(wn + (lane >> 4) * 8 + (lane & 7)) * RSTR +
                              ((lane >> 3) & 1) * 16;

    float c[2][8][4];
#pragma unroll
    for (int mt = 0; mt < 2; mt++)
#pragma unroll
        for (int nt = 0; nt < 8; nt++)
#pragma unroll
            for (int i = 0; i < 4; i++) c[mt][nt][i] = 0.f;

    // one chunk = 64 halves of K (s = c>>1, kh = (c&1)*64)
    auto copy_chunk = [&](int cidx, int b) {
        int s = cidx >> 1;
        int kh = (cidx & 1) * 64;
        const __half* Asrc = g_Gh[side][s] + kh;
        const __half* Bsrc = g_Wn[s] + kh;
        char* sa = smem + b * BUFB;
        char* sbuf = smem + (2 + b) * BUFB;
#pragma unroll
        for (int i = 0; i < 4; i++) {
            int q = t + 256 * i;            // 0..1023
            int row = q >> 3;               // 0..127
            int c16 = (q & 7) * 16;         // byte col (8 halves per quad)
            int gr = row0 + row;
            if (gr > NUSERS - 1) gr = NUSERS - 1;  // clamp; stores guarded
            cp16(sa + row * RSTR + c16, Asrc + (size_t)gr * 128 + (c16 >> 1));
            cp16(sbuf + row * RSTR + c16, Bsrc + (size_t)row * 128 + (c16 >> 1));
        }
        asm volatile("cp.async.commit_group;" ::: "memory");
    };

    copy_chunk(0, 0);
    int buf = 0;

#pragma unroll 1
    for (int cc = 0; cc < NCHUNKS; cc++) {
        if (cc + 1 < NCHUNKS) {
            copy_chunk(cc + 1, buf ^ 1);
            asm volatile("cp.async.wait_group 1;" ::: "memory");
        } else {
            asm volatile("cp.async.wait_group 0;" ::: "memory");
        }
        __syncthreads();

        const uint32_t aBase = sb + buf * BUFB + aRowByte;
        const uint32_t bBase = sb + (2 + buf) * BUFB + bRowByte;
#pragma unroll
        for (int ks = 0; ks < 4; ks++) {      // four k16 steps per chunk
            uint32_t a[2][4], bf[4][4];
#pragma unroll
            for (int mt = 0; mt < 2; mt++)
                LDSM_X4(a[mt], aBase + mt * (16 * RSTR) + ks * 32);
#pragma unroll
            for (int nt2 = 0; nt2 < 4; nt2++)
                LDSM_X4(bf[nt2], bBase + nt2 * (16 * RSTR) + ks * 32);
#pragma unroll
            for (int mt = 0; mt < 2; mt++)
#pragma unroll
                for (int nt = 0; nt < 8; nt++) {
                    int nt2 = nt >> 1, sub = (nt & 1) * 2;
                    MMA_F16(c[mt][nt], a[mt], bf[nt2][sub], bf[nt2][sub + 1]);
                }
        }
        buf ^= 1;
        __syncthreads();
    }

    float* O = out + (size_t)side * NUSERS * 128;
#pragma unroll
    for (int mt = 0; mt < 2; mt++) {
        int r0 = row0 + wm + mt * 16 + gid;
        int r1 = r0 + 8;
#pragma unroll
        for (int nt = 0; nt < 8; nt++) {
            int cg = wn + nt * 8 + tig * 2;
            if (r0 < NUSERS)
                *(float2*)&O[(size_t)r0 * 128 + cg] =
                    make_float2(fmaxf(c[mt][nt][0], 0.f), fmaxf(c[mt][nt][1], 0.f));
            if (r1 < NUSERS)
                *(float2*)&O[(size_t)r1 * 128 + cg] =
                    make_float2(fmaxf(c[mt][nt][2], 0.f), fmaxf(c[mt][nt][3], 0.f));
        }
    }
}

// ---------------------------------------------------------------------------
// kernel_launch
// ---------------------------------------------------------------------------
extern "C" void kernel_launch(void* const* d_in, const int* in_sizes, int n_in,
                              void* d_out, int out_size) {
    const float* U = (const float*)d_in[0];
    const float* It = (const float*)d_in[1];
    const float* W = (const float*)d_in[2];
    const int* u_rows = (const int*)d_in[3];
    const int* u_cols = (const int*)d_in[4];
    const float* u_vals = (const float*)d_in[5];
    const int* i_rows = (const int*)d_in[6];
    const int* i_cols = (const int*)d_in[7];
    const float* i_vals = (const float*)d_in[8];
    float* out = (float*)d_out;

    wcum_kernel<<<DIN, DOUT>>>(W);
    cvt_kernel<<<(2 * NUSERS * 128 / 4 + 255) / 256, 256>>>(U, It);

    // --- CSR build ---
    zero_kernel<<<(NBINS + 255) / 256, 256>>>();
    const int eb = (TOTE + 255) / 256;
    hist_kernel<<<eb, 256>>>(u_rows, i_rows);
    scan1_kernel<<<NCHUNK, 256>>>();
    scan2_kernel<<<1, 1024>>>();
    scan3_kernel<<<NCHUNK, 256>>>();
    scatter_kernel<<<eb, 256>>>(u_rows, u_cols, u_vals, i_rows, i_cols, i_vals);

    // --- atomic-free fp16 gather SpMM ---
    gather_kernel<<<(2 * NUSERS * 32 + 255) / 256, 256>>>();

    // --- ldmatrix fp16 K=640 GEMM + fused ReLU ---
    cudaFuncSetAttribute(gemm_kernel, cudaFuncAttributeMaxDynamicSharedMemorySize, GT_TOTAL);
    dim3 g(MTILES, 2);
    gemm_kernel<<<g, 256, GT_TOTAL>>>(out);
}